// round 17
// baseline (speedup 1.0000x reference)
#include <cuda_runtime.h>
#include <cuda_fp16.h>
#include <cstdint>

// ============================================================================
// x (64,112,112,64) f32 NHWC; kernels (3,3,64,64) f32 HWIO (+-1); beta (64).
// out = conv3x3_SAME(BN_train(x), kernels), fp32.
//
// BN folded into GEMM; padded border = fp16(-shift/scale). Implicit GEMM
// mma.sync.m16n8k16.f16. Conv: 384 thr = 6 pairs; warp tile 64x32 over a
// pair-owned QUAD of 16-px row-windows. Rows live in a 2-SLOT ring (chunk j
// reads only row j; slot (r&1) recycled after the post-MMA bar, wait_group 1)
// -> smem funds 4 windows: LDS bytes/MAC 0.125 -> 0.094 (R16: L1=73% wall).
// ============================================================================

#define N_  64
#define H_  112
#define W_  112
#define C_  64
#define HP  114
#define WP  114
#define M_CNT (N_*H_*W_)
#define NVEC  ((size_t)M_CNT * 16)
#define NPIX  (N_*H_*W_)
#define HW_   (H_*W_)                // 12544
#define PIXB  (C_*2)                 // 128 B per padded pixel
#define ROWPB (WP*PIXB)              // 14592 B per padded row
#define SBLK  1024                   // stats blocks

#define CTATILE 384
#define NT ((NPIX + CTATILE - 1) / CTATILE)   // 2091 (last tile 256 px)

// B: [3 dy][192 k][64 co] fp16, 128B rows, XOR swizzle (k&7)<<4
#define BROWB  128
#define BCHUNKB (192*BROWB)          // 24576
#define B_BYTES (3*BCHUNKB)          // 73728

// A: per-PAIR 4 windows x 2 slots x (18 px x 128B)
#define RBUF 2304                    // 18*128
#define WINSLOT (2*RBUF)             // 4608 per window
#define PPB (4*WINSLOT)              // 18432 per pair
#define SM_A0  B_BYTES
#define CONV_SMEM (B_BYTES + 6*PPB)  // 184320

// ---------------- persistent device scratch (zero-init .bss) ----------------
__device__ __align__(16) unsigned short g_xf[(size_t)N_ * HP * WP * C_];
__device__ __align__(16) unsigned short g_wb[3 * 192 * 64];
__device__ float g_psum[SBLK * C_];
__device__ float g_psq[SBLK * C_];
__device__ float g_scale[C_];
__device__ float g_shift[C_];
__device__ float g_bias[C_];
__device__ unsigned short g_bord[C_];

// ============================ PTX helpers ===================================
__device__ __forceinline__ uint32_t smem_to_u32(const void* p) {
    uint32_t a;
    asm("{ .reg .u64 t; cvta.to.shared.u64 t, %1; cvt.u32.u64 %0, t; }"
        : "=r"(a) : "l"(p));
    return a;
}

#define LDSM_X4(r, addr) \
    asm volatile("ldmatrix.sync.aligned.m8n8.x4.shared.b16 {%0,%1,%2,%3}, [%4];" \
        : "=r"((r)[0]), "=r"((r)[1]), "=r"((r)[2]), "=r"((r)[3]) : "r"(addr))

#define LDSM_X4_T(r, addr) \
    asm volatile("ldmatrix.sync.aligned.m8n8.x4.trans.shared.b16 {%0,%1,%2,%3}, [%4];" \
        : "=r"((r)[0]), "=r"((r)[1]), "=r"((r)[2]), "=r"((r)[3]) : "r"(addr))

#define MMA16816(c, a, b0v, b1v) \
    asm volatile("mma.sync.aligned.m16n8k16.row.col.f32.f16.f16.f32 " \
        "{%0,%1,%2,%3}, {%4,%5,%6,%7}, {%8,%9}, {%0,%1,%2,%3};" \
        : "+f"((c)[0]), "+f"((c)[1]), "+f"((c)[2]), "+f"((c)[3]) \
        : "r"((a)[0]), "r"((a)[1]), "r"((a)[2]), "r"((a)[3]), \
          "r"(b0v), "r"(b1v))

#define CP_ASYNC16(dst_s, src_g) \
    asm volatile("cp.async.cg.shared.global [%0], [%1], 16;" \
        :: "r"(dst_s), "l"(src_g))
#define CP_COMMIT() asm volatile("cp.async.commit_group;" ::: "memory")
#define CP_WAIT1()  asm volatile("cp.async.wait_group 1;" ::: "memory")
#define BAR_SYNC(id) asm volatile("bar.sync %0, 64;" :: "r"(id) : "memory")

__device__ __forceinline__ unsigned short f2h(float f) {
    __half h = __float2half_rn(f);
    return *reinterpret_cast<unsigned short*>(&h);
}

// ---------------------------------------------------------------------------
// Launch 0: per-channel partial moments (per-block) + raw-x fp16 conversion.
__global__ void __launch_bounds__(256) k_stats_conv(const float* __restrict__ x) {
    __shared__ float ssum[C_];
    __shared__ float ssq[C_];
    int tid = threadIdx.x;
    if (tid < C_) { ssum[tid] = 0.0f; ssq[tid] = 0.0f; }
    __syncthreads();

    const float4* xv = (const float4*)x;
    uint2* of = (uint2*)g_xf;
    int g = tid & 15;
    float4 s = make_float4(0.f, 0.f, 0.f, 0.f);
    float4 q = make_float4(0.f, 0.f, 0.f, 0.f);
    size_t stride = (size_t)gridDim.x * blockDim.x;
    for (size_t i = (size_t)blockIdx.x * blockDim.x + tid; i < NVEC; i += stride) {
        float4 v = xv[i];
        s.x += v.x; s.y += v.y; s.z += v.z; s.w += v.w;
        q.x += v.x * v.x; q.y += v.y * v.y; q.z += v.z * v.z; q.w += v.w * v.w;

        size_t pix = i >> 4;
        int n   = (int)(pix / HW_);
        int rem = (int)(pix % HW_);
        int h   = rem / W_;
        int w   = rem % W_;
        unsigned short h0 = f2h(v.x), h1 = f2h(v.y), h2 = f2h(v.z), h3 = f2h(v.w);
        size_t dpix = ((size_t)n * HP + (h + 1)) * WP + (w + 1);
        of[dpix * 16 + g] = make_uint2((uint32_t)h0 | ((uint32_t)h1 << 16),
                                       (uint32_t)h2 | ((uint32_t)h3 << 16));
    }
    atomicAdd(&ssum[g * 4 + 0], s.x); atomicAdd(&ssq[g * 4 + 0], q.x);
    atomicAdd(&ssum[g * 4 + 1], s.y); atomicAdd(&ssq[g * 4 + 1], q.y);
    atomicAdd(&ssum[g * 4 + 2], s.z); atomicAdd(&ssq[g * 4 + 2], q.z);
    atomicAdd(&ssum[g * 4 + 3], s.w); atomicAdd(&ssq[g * 4 + 3], q.w);
    __syncthreads();
    if (tid < C_) {
        g_psum[blockIdx.x * C_ + tid] = ssum[tid];
        g_psq [blockIdx.x * C_ + tid] = ssq[tid];
    }
}

// ---------------------------------------------------------------------------
// Launch 1: parallel reduce partials -> scale/shift/border + bias. 512 thr.
__global__ void __launch_bounds__(512) k_finprep(const float* __restrict__ beta,
                                                 const float* __restrict__ kw) {
    __shared__ float rs[C_ * 8];
    __shared__ float rq[C_ * 8];
    int tid = threadIdx.x;
    int c = tid >> 3;
    int k = tid & 7;
    float s = 0.0f, q = 0.0f;
    for (int b = k; b < SBLK; b += 8) {
        s += g_psum[b * C_ + c];
        q += g_psq [b * C_ + c];
    }
    rs[tid] = s; rq[tid] = q;
    __syncthreads();
    if (tid < C_) {
        float ts = 0.0f, tq = 0.0f;
        #pragma unroll
        for (int i = 0; i < 8; i++) { ts += rs[tid * 8 + i]; tq += rq[tid * 8 + i]; }
        const float inv_m = 1.0f / (float)M_CNT;
        float m  = ts * inv_m;
        float v  = tq * inv_m - m * m;
        float sc = rsqrtf(v + 1e-5f);
        float sh = beta[tid] - m * sc;
        g_scale[tid] = sc;
        g_shift[tid] = sh;
        g_bord[tid]  = f2h(-sh / sc);
    }
    __syncthreads();
    {
        float acc = 0.0f;
        for (int t = k; t < 9; t += 8)
            for (int ci = 0; ci < 64; ci++)
                acc += kw[((size_t)t * 64 + ci) * 64 + c] * g_shift[ci];
        rs[tid] = acc;
    }
    __syncthreads();
    if (tid < C_) {
        float a = 0.0f;
        #pragma unroll
        for (int i = 0; i < 8; i++) a += rs[tid * 8 + i];
        g_bias[tid] = a;
    }
}

// ---------------------------------------------------------------------------
// Launch 2: swizzled B image + border fill.
__global__ void __launch_bounds__(256) k_bw(const float* __restrict__ kw) {
    int i = blockIdx.x * blockDim.x + threadIdx.x;
    if (i < 36864) {
        int cout = i & 63;
        int cin  = (i >> 6) & 63;
        int t    = i >> 12;            // dy*3+dx
        int dy = t / 3, dx = t % 3;
        float v = kw[((size_t)t * 64 + cin) * 64 + cout] * g_scale[cin];
        int kk = dx * 64 + cin;
        int off = kk * BROWB + cout * 2;
        off ^= (kk & 7) << 4;
        *(unsigned short*)((char*)g_wb + (size_t)dy * BCHUNKB + off) = f2h(v);
        return;
    }
    int idx = i - 36864;
    if (idx >= 64 * 452 * 16) return;
    int g   = idx & 15;
    int bp  = (idx >> 4) % 452;
    int img = (idx >> 4) / 452;
    int h, w;
    if (bp < 114)      { h = 0;   w = bp; }
    else if (bp < 228) { h = 113; w = bp - 114; }
    else { int j = bp - 228; h = 1 + (j >> 1); w = (j & 1) ? 113 : 0; }
    const unsigned short* bd = g_bord;
    uint32_t v0 = (uint32_t)bd[g*4+0] | ((uint32_t)bd[g*4+1] << 16);
    uint32_t v1 = (uint32_t)bd[g*4+2] | ((uint32_t)bd[g*4+3] << 16);
    ((uint2*)g_xf)[(((size_t)img * HP + h) * WP + w) * 16 + g] = make_uint2(v0, v1);
}

// ---------------------------------------------------------------------------
// window base for (tile, pair, win) for a staging thread at column col.
__device__ __forceinline__ const char* win_src(const char* gx, int tile,
                                               int pr, int win, int col) {
    int gp = tile * CTATILE + pr * 64 + win * 16;
    if (gp > NPIX - 16) gp = NPIX - 16;       // clamp (tail duplicates, discarded)
    int n   = gp / HW_;
    int rem = gp % HW_;
    int h   = rem / W_;
    int w0  = rem % W_;
    return gx + (((size_t)n * HP + h) * WP + w0 + col) * PIXB;
}

// ---------------------------------------------------------------------------
// Launch 3 (profiled): conv. 384 thr = 6 pairs; warp tile 64x32 (quad window).
// 2-slot row ring per window; per chunk: wait1 -> bar -> MMA -> bar -> issue
// row rr+2 -> commit.
__global__ void __launch_bounds__(384, 1)
k_conv(float* __restrict__ out) {
    extern __shared__ __align__(1024) unsigned char smem[];
    uint32_t sb = smem_to_u32(smem);
    int tid = threadIdx.x;

    // stage B once (pre-swizzled image)
    {
        const uint4* src = (const uint4*)g_wb;
        uint4* dst = (uint4*)smem;
        for (int i = tid; i < B_BYTES / 16; i += 384) dst[i] = src[i];
    }
    __syncthreads();

    int lane = tid & 31;
    int wid  = tid >> 5;           // 0..11
    int pr   = wid >> 1;           // pair 0..5 -> pixels pr*64..+64 (4 windows)
    int nw   = wid & 1;            // n-half: couts nw*32..+32
    int sel  = lane >> 3;
    int l7   = lane & 7;
    int barid = pr + 1;

    uint32_t pairbuf = sb + SM_A0 + (uint32_t)pr * PPB;

    // A lane addressing (per dx), window-invariant; window adds w*WINSLOT.
    int p_row = (sel & 1) * 8 + l7;
    uint32_t abase[3], amask[3];
    #pragma unroll
    for (int dx = 0; dx < 3; dx++) {
        int qq = p_row + dx;
        abase[dx] = (uint32_t)(qq * 128 + (sel >> 1) * 16);
        amask[dx] = (uint32_t)((qq & 7) << 4);
    }

    uint32_t b_lane = sb + (uint32_t)(((sel & 1) * 8 + l7) * BROWB);
    uint32_t bo0 = (uint32_t)((((sel >> 1) * 16) + nw * 64)      ^ (l7 << 4));
    uint32_t bo1 = (uint32_t)((((sel >> 1) * 16) + nw * 64 + 32) ^ (l7 << 4));

    // staging: 64 thr/pair; per row: 72 blocks (4 win x 18 col) of 128B.
    // thread pt does block pt (win_a=pt/18, col_a=pt%18); pt<8 also block
    // 64+pt (win 3, col 10+pt).
    int pt    = tid & 63;
    int win_a = pt / 18;
    int col_a = pt % 18;
    int hasb  = (pt < 8);
    int col_b = 10 + pt;
    uint32_t dstA = pairbuf + (uint32_t)win_a * WINSLOT;   // + slot*RBUF + swz
    uint32_t dstB = pairbuf + 3u * WINSLOT;
    uint32_t sbA = (uint32_t)(col_a * 128), smA = (uint32_t)((col_a & 7) << 4);
    uint32_t sbB = (uint32_t)(col_b * 128), smB = (uint32_t)((col_b & 7) << 4);
    const char* gx = (const char*)g_xf;

    int cq = lane & 3;
    float bia0[4], bia1[4];
    #pragma unroll
    for (int nf = 0; nf < 4; nf++) {
        bia0[nf] = g_bias[nw * 32 + nf * 8 + 2 * cq];
        bia1[nf] = g_bias[nw * 32 + nf * 8 + 2 * cq + 1];
    }

    // current-tile staging sources for this thread
    const char* curA = win_src(gx, blockIdx.x, pr, win_a, col_a);
    const char* curB = hasb ? win_src(gx, blockIdx.x, pr, 3, col_b) : nullptr;

    // prologue: stage rows 0,1 of first tile (slots 0,1)
    #pragma unroll
    for (int jj = 0; jj < 2; jj++) {
        uint32_t dA = dstA + (uint32_t)jj * RBUF;
        const char* sA = curA + (size_t)jj * ROWPB;
        #pragma unroll
        for (int i = 0; i < 8; i++) CP_ASYNC16(dA + ((sbA + i * 16) ^ smA), sA + i * 16);
        if (hasb) {
            uint32_t dB = dstB + (uint32_t)jj * RBUF;
            const char* sB = curB + (size_t)jj * ROWPB;
            #pragma unroll
            for (int i = 0; i < 8; i++) CP_ASYNC16(dB + ((sbB + i * 16) ^ smB), sB + i * 16);
        }
        CP_COMMIT();
    }

    uint32_t rr = 0;   // free-running row counter (slot = rr&1)
    for (int tile = blockIdx.x; tile < NT; tile += gridDim.x) {
        int t2 = tile + gridDim.x;
        const char* nxtA = nullptr;
        const char* nxtB = nullptr;
        if (t2 < NT) {
            nxtA = win_src(gx, t2, pr, win_a, col_a);
            if (hasb) nxtB = win_src(gx, t2, pr, 3, col_b);
        }

        float c[64];
        #pragma unroll
        for (int i = 0; i < 64; i++) c[i] = 0.0f;

        #pragma unroll 1
        for (int j = 0; j < 3; j++) {
            CP_WAIT1();
            BAR_SYNC(barid);

            uint32_t slotoff = (rr & 1) * RBUF;
            uint32_t Bbase = b_lane + (uint32_t)j * BCHUNKB;

            #pragma unroll
            for (int s = 0; s < 12; s++) {
                const int dx = s >> 2;
                uint32_t aoff = ((abase[dx] + (s & 3) * 32) ^ amask[dx]) + slotoff;
                uint32_t ra0[4], ra1[4], ra2[4], ra3[4], rb0[4], rb1[4];
                LDSM_X4(ra0, pairbuf + aoff);
                LDSM_X4(ra1, pairbuf + WINSLOT + aoff);
                LDSM_X4(ra2, pairbuf + 2 * WINSLOT + aoff);
                LDSM_X4(ra3, pairbuf + 3 * WINSLOT + aoff);
                uint32_t Bs = Bbase + (uint32_t)s * (16 * BROWB);
                LDSM_X4_T(rb0, Bs + bo0);
                LDSM_X4_T(rb1, Bs + bo1);

                MMA16816(c +  0, ra0, rb0[0], rb0[1]);
                MMA16816(c +  4, ra0, rb0[2], rb0[3]);
                MMA16816(c +  8, ra0, rb1[0], rb1[1]);
                MMA16816(c + 12, ra0, rb1[2], rb1[3]);
                MMA16816(c + 16, ra1, rb0[0], rb0[1]);
                MMA16816(c + 20, ra1, rb0[2], rb0[3]);
                MMA16816(c + 24, ra1, rb1[0], rb1[1]);
                MMA16816(c + 28, ra1, rb1[2], rb1[3]);
                MMA16816(c + 32, ra2, rb0[0], rb0[1]);
                MMA16816(c + 36, ra2, rb0[2], rb0[3]);
                MMA16816(c + 40, ra2, rb1[0], rb1[1]);
                MMA16816(c + 44, ra2, rb1[2], rb1[3]);
                MMA16816(c + 48, ra3, rb0[0], rb0[1]);
                MMA16816(c + 52, ra3, rb0[2], rb0[3]);
                MMA16816(c + 56, ra3, rb1[0], rb1[1]);
                MMA16816(c + 60, ra3, rb1[2], rb1[3]);
            }

            // both warps done with slot (rr&1) -> refill with row rr+2
            BAR_SYNC(barid);
            {
                const char* sA = nullptr; const char* sB = nullptr;
                if (j == 0)      { sA = curA + 2 * (size_t)ROWPB;
                                   sB = hasb ? curB + 2 * (size_t)ROWPB : nullptr; }
                else if (nxtA)   { sA = nxtA + (size_t)(j - 1) * ROWPB;
                                   sB = hasb ? nxtB + (size_t)(j - 1) * ROWPB : nullptr; }
                if (sA) {
                    uint32_t dA = dstA + slotoff;
                    #pragma unroll
                    for (int i = 0; i < 8; i++)
                        CP_ASYNC16(dA + ((sbA + i * 16) ^ smA), sA + i * 16);
                    if (sB) {
                        uint32_t dB = dstB + slotoff;
                        #pragma unroll
                        for (int i = 0; i < 8; i++)
                            CP_ASYNC16(dB + ((sbB + i * 16) ^ smB), sB + i * 16);
                    }
                }
                CP_COMMIT();
            }
            rr++;
        }

        // epilogue: add bias, store 4 windows x 16 px x 32 couts (predicated)
        int r = lane >> 2;
        #pragma unroll
        for (int w = 0; w < 4; w++) {
            int pix0 = tile * CTATILE + pr * 64 + w * 16 + r;
            float* p0 = out + (size_t)pix0 * 64 + nw * 32 + 2 * cq;
            float* p1 = p0 + 8 * 64;
            if (pix0 < NPIX) {
                #pragma unroll
                for (int nf = 0; nf < 4; nf++)
                    *(float2*)(p0 + nf * 8) = make_float2(c[w*16 + nf*4 + 0] + bia0[nf],
                                                          c[w*16 + nf*4 + 1] + bia1[nf]);
            }
            if (pix0 + 8 < NPIX) {
                #pragma unroll
                for (int nf = 0; nf < 4; nf++)
                    *(float2*)(p1 + nf * 8) = make_float2(c[w*16 + nf*4 + 2] + bia0[nf],
                                                          c[w*16 + nf*4 + 3] + bia1[nf]);
            }
        }

        curA = nxtA;
        curB = nxtB;
    }
}

// ---------------------------------------------------------------------------
extern "C" void kernel_launch(void* const* d_in, const int* in_sizes, int n_in,
                              void* d_out, int out_size) {
    const float* x    = (const float*)d_in[0];
    const float* kw   = (const float*)d_in[1];
    const float* beta = (const float*)d_in[2];
    float* out = (float*)d_out;
    (void)in_sizes; (void)n_in; (void)out_size;

    cudaFuncSetAttribute(k_conv, cudaFuncAttributeMaxDynamicSharedMemorySize, CONV_SMEM);

    k_stats_conv<<<SBLK, 256>>>(x);                              // launch 0
    k_finprep<<<1, 512>>>(beta, kw);                             // launch 1
    k_bw<<<(36864 + 64 * 452 * 16 + 255) / 256, 256>>>(kw);      // launch 2
    k_conv<<<152, 384, CONV_SMEM>>>(out);                        // launch 3 (profiled)
}